// round 4
// baseline (speedup 1.0000x reference)
#include <cuda_runtime.h>
#include <cuda_bf16.h>
#include <math.h>

// Problem constants
#define CIN   256
#define COUT  128
#define KK    9
#define H0    64
#define W0    64
#define HH    128   // upsampled H
#define WW    128   // upsampled W
#define NB    2

#define CI_CHUNK 16

// Scratch (device globals — no allocations allowed)
__device__ float g_up[NB * COUT * HH * WW];          // 16 MB: transposed-conv output
__device__ float g_wr[KK * COUT * CIN];              // deform weights: [kk][ci][o]
__device__ float g_wt2[KK * CIN * COUT];             // tconv weights: [ky][kx][ci][co] (pre-flipped)
__device__ int   g_sy[NB][KK];
__device__ int   g_sx[NB][KK];
__device__ float g_cw[NB][KK][4];

// packed fp32x2 FMA: d = a * b + d   (SASS FFMA2; only reachable via PTX f32x2)
__device__ __forceinline__ void fma2(unsigned long long& d,
                                     unsigned long long a,
                                     unsigned long long b) {
    asm("fma.rn.f32x2 %0, %1, %2, %0;" : "+l"(d) : "l"(a), "l"(b));
}

// ---------------------------------------------------------------------------
// Kernel 1: reorder weights into lane-contiguous layouts
// ---------------------------------------------------------------------------
__global__ void reorder_kernel(const float* __restrict__ tw) {
    int i = blockIdx.x * blockDim.x + threadIdx.x;
    if (i >= KK * COUT * CIN) return;
    // g_wr[kk][ci][o] = tw[o][ci][kk]
    {
        int o  = i & (CIN - 1);
        int ci = (i >> 8) & (COUT - 1);
        int kk = i >> 15;
        g_wr[i] = tw[(o * COUT + ci) * KK + kk];
    }
    // g_wt2[(ky*3+kx)][ci][co] = tw[ci][co][2-ky][2-kx]
    {
        int co = i & (COUT - 1);
        int ci = (i >> 7) & (CIN - 1);
        int k2 = i >> 15;
        int ky = k2 / 3, kx = k2 % 3;
        g_wt2[i] = tw[(ci * COUT + co) * KK + (2 - ky) * 3 + (2 - kx)];
    }
}

// ---------------------------------------------------------------------------
// Kernel 2: offset branch (center-tap only, spatially constant) + bilinear
//           decomposition into integer shifts + 4 corner weights.
// ---------------------------------------------------------------------------
__global__ void offsets_kernel(const float* __restrict__ lat,
                               const float* __restrict__ w1,
                               const float* __restrict__ b1,
                               const float* __restrict__ w2,
                               const float* __restrict__ b2) {
    __shared__ float h[NB][64];
    __shared__ float oc[NB][18];
    int tid = threadIdx.x;
    if (tid < NB * 64) {
        int n = tid >> 6, j = tid & 63;
        float s = b1[j];
        #pragma unroll 4
        for (int i = 0; i < COUT; i++)
            s += lat[n * COUT + i] * w1[(j * COUT + i) * KK + 4];
        h[n][j] = fmaxf(s, 0.f);
    }
    __syncthreads();
    if (tid < NB * 18) {
        int n = tid / 18, c = tid % 18;
        float s = b2[c];
        #pragma unroll 4
        for (int j = 0; j < 64; j++)
            s += h[n][j] * w2[(c * 64 + j) * KK + 4];
        oc[n][c] = tanhf(s);
    }
    __syncthreads();
    if (tid < NB * KK) {
        int n = tid / KK, kk = tid % KK;
        float oy = oc[n][2 * kk], ox = oc[n][2 * kk + 1];
        float fy = floorf(oy), fx = floorf(ox);
        float dy = oy - fy,  dx = ox - fx;
        g_sy[n][kk] = (kk / 3 - 1) + (int)fy;
        g_sx[n][kk] = (kk % 3 - 1) + (int)fx;
        g_cw[n][kk][0] = (1.f - dy) * (1.f - dx);
        g_cw[n][kk][1] = (1.f - dy) * dx;
        g_cw[n][kk][2] = dy * (1.f - dx);
        g_cw[n][kk][3] = dy * dx;
    }
}

// ---------------------------------------------------------------------------
// Kernel 3: transposed conv as parity-split GEMM with packed f32x2 FMA.
// Block: (Y, x-parity sX, n). Output tile: 128 co x 64 px (X = 2*j + sX).
// Thread: 8 co x 4 px (2 px-pairs). Weights duplicated in smem for pairing.
// ---------------------------------------------------------------------------
__global__ void __launch_bounds__(256)
tconv_kernel(const float* __restrict__ x, const float* __restrict__ wt2) {
    const int Y   = blockIdx.x;
    const int sX  = blockIdx.y;
    const int n   = blockIdx.z;
    const int tid = threadIdx.x;

    __shared__ __align__(16) float wA2[CI_CHUNK][256];   // dup pairs over co
    __shared__ __align__(16) float xs[CI_CHUNK][64];

    const int og = tid >> 4;     // 0..15: co group of 8
    const int pg = tid & 15;     // 0..15: px group of 4 (2 pairs)

    unsigned long long acc[8][2];
    #pragma unroll
    for (int i = 0; i < 8; i++) { acc[i][0] = 0ULL; acc[i][1] = 0ULL; }

    int kylist[2]; int nky = 0;
    if (Y & 1) {
        kylist[nky++] = 0;
        if (Y + 1 < HH) kylist[nky++] = 2;
    } else {
        kylist[nky++] = 1;
    }
    int kxlist[2]; int nkx = 0;
    if (sX == 0) { kxlist[nkx++] = 1; }
    else         { kxlist[nkx++] = 0; kxlist[nkx++] = 2; }

    for (int a_ = 0; a_ < nky; a_++) {
        const int ky = kylist[a_];
        const int y0 = (Y + ky - 1) >> 1;
        const float* xbase = x + (n * CIN * H0 + y0) * W0;
        for (int b_ = 0; b_ < nkx; b_++) {
            const int kx = kxlist[b_];
            const int d  = (sX + kx - 1) >> 1;     // 0 or 1
            const float* wtap = wt2 + (ky * 3 + kx) * CIN * COUT;

            for (int c0 = 0; c0 < CIN; c0 += CI_CHUNK) {
                __syncthreads();
                // weight tile, duplicated pairs: 16ci x 64 float2 = 1024 / 256thr
                #pragma unroll
                for (int r = 0; r < 4; r++) {
                    int idx = tid + r * 256;
                    int ci = idx >> 6, t = idx & 63;
                    float2 w2 = *(const float2*)&wtap[(c0 + ci) * COUT + 2 * t];
                    *(float4*)&wA2[ci][4 * t] = make_float4(w2.x, w2.x, w2.y, w2.y);
                }
                // input tile: 16ci x 64 px
                #pragma unroll
                for (int r = 0; r < 4; r++) {
                    int idx = tid + r * 256;
                    int ci = idx >> 6, j = idx & 63;
                    int src = j + d;
                    xs[ci][j] = (src < W0) ? xbase[(c0 + ci) * H0 * W0 + src] : 0.f;
                }
                __syncthreads();

                #pragma unroll 4
                for (int ci = 0; ci < CI_CHUNK; ci++) {
                    const ulonglong2* wp = (const ulonglong2*)&wA2[ci][og * 16];
                    ulonglong2 a01 = wp[0], a23 = wp[1], a45 = wp[2], a67 = wp[3];
                    ulonglong2 b01 = *(const ulonglong2*)&xs[ci][pg * 4];
                    unsigned long long av[8] = {a01.x, a01.y, a23.x, a23.y,
                                                a45.x, a45.y, a67.x, a67.y};
                    unsigned long long bv[2] = {b01.x, b01.y};
                    #pragma unroll
                    for (int i = 0; i < 8; i++) {
                        fma2(acc[i][0], av[i], bv[0]);
                        fma2(acc[i][1], av[i], bv[1]);
                    }
                }
            }
        }
    }

    #pragma unroll
    for (int i = 0; i < 8; i++) {
        float* up = g_up + ((n * COUT + og * 8 + i) * HH + Y) * WW + sX;
        #pragma unroll
        for (int j = 0; j < 2; j++) {
            unsigned long long v = acc[i][j];
            float lo = __uint_as_float((unsigned)(v & 0xffffffffULL));
            float hi = __uint_as_float((unsigned)(v >> 32));
            up[2 * (pg * 4 + 2 * j)]     = lo;
            up[2 * (pg * 4 + 2 * j + 1)] = hi;
        }
    }
}

// ---------------------------------------------------------------------------
// Kernel 4: deformable conv as GEMM with packed f32x2 FMA.
// Block: (y, o-tile of 128, n). Output tile: 128 o x 128 px (full row).
// Thread: 8 o x 8 px (4 px-pairs). Weights duplicated in smem for pairing.
// ---------------------------------------------------------------------------
__global__ void __launch_bounds__(256, 2)
deform_kernel(const float* __restrict__ wr, float* __restrict__ out) {
    const int y   = blockIdx.x;
    const int ob  = blockIdx.y;   // 0,1: which 128 of the 256 outputs
    const int n   = blockIdx.z;
    const int tid = threadIdx.x;

    __shared__ __align__(16) float wA2[CI_CHUNK][256];   // dup pairs over o
    __shared__ __align__(16) float s[CI_CHUNK][128];
    __shared__ int   ssy[KK], ssx[KK];
    __shared__ float scw[KK][4];
    if (tid < KK) { ssy[tid] = g_sy[n][tid]; ssx[tid] = g_sx[n][tid]; }
    if (tid < KK * 4) ((float*)scw)[tid] = ((const float*)g_cw[n])[tid];
    __syncthreads();

    const int og = tid >> 4;      // 0..15: o group of 8
    const int pg = tid & 15;      // 0..15: px group of 8 (4 pairs)

    unsigned long long acc[8][4];
    #pragma unroll
    for (int i = 0; i < 8; i++)
        #pragma unroll
        for (int j = 0; j < 4; j++) acc[i][j] = 0ULL;

    const float* upn = g_up + n * COUT * HH * WW;

    for (int kk = 0; kk < KK; kk++) {
        const int   sy  = ssy[kk], sx = ssx[kk];
        const float c00 = scw[kk][0], c01 = scw[kk][1];
        const float c10 = scw[kk][2], c11 = scw[kk][3];
        const int   yy0 = y + sy;
        const bool  yin0 = (unsigned)yy0 < HH;
        const bool  yin1 = (unsigned)(yy0 + 1) < HH;
        const float* wkk = wr + kk * COUT * CIN + ob * 128;

        for (int c0 = 0; c0 < COUT; c0 += CI_CHUNK) {
            __syncthreads();
            // weight tile, duplicated pairs: 16ci x 64 float2 = 1024 / 256thr
            #pragma unroll
            for (int r = 0; r < 4; r++) {
                int idx = tid + r * 256;
                int ci = idx >> 6, t = idx & 63;
                float2 w2 = *(const float2*)&wkk[(c0 + ci) * CIN + 2 * t];
                *(float4*)&wA2[ci][4 * t] = make_float4(w2.x, w2.x, w2.y, w2.y);
            }
            // sampled tile: 16ci x 128 px = 2048 / 256thr = 8 each
            #pragma unroll
            for (int r = 0; r < 8; r++) {
                int idx = tid + r * 256;
                int ci = idx >> 7, px = idx & 127;
                int xx = px + sx;
                bool xin0 = (unsigned)xx < WW;
                bool xin1 = (unsigned)(xx + 1) < WW;
                const float* upc = upn + (c0 + ci) * HH * WW;
                float v = 0.f;
                if (yin0) {
                    const float* row = upc + yy0 * WW;
                    if (xin0) v += c00 * row[xx];
                    if (xin1) v += c01 * row[xx + 1];
                }
                if (yin1) {
                    const float* row = upc + (yy0 + 1) * WW;
                    if (xin0) v += c10 * row[xx];
                    if (xin1) v += c11 * row[xx + 1];
                }
                s[ci][px] = v;
            }
            __syncthreads();

            #pragma unroll 4
            for (int ci = 0; ci < CI_CHUNK; ci++) {
                const ulonglong2* wp = (const ulonglong2*)&wA2[ci][og * 16];
                ulonglong2 a01 = wp[0], a23 = wp[1], a45 = wp[2], a67 = wp[3];
                const ulonglong2* sp = (const ulonglong2*)&s[ci][pg * 8];
                ulonglong2 b01 = sp[0], b23 = sp[1];
                unsigned long long av[8] = {a01.x, a01.y, a23.x, a23.y,
                                            a45.x, a45.y, a67.x, a67.y};
                unsigned long long bv[4] = {b01.x, b01.y, b23.x, b23.y};
                #pragma unroll
                for (int i = 0; i < 8; i++)
                    #pragma unroll
                    for (int j = 0; j < 4; j++)
                        fma2(acc[i][j], av[i], bv[j]);
            }
        }
    }

    #pragma unroll
    for (int i = 0; i < 8; i++) {
        float* op = out + ((n * CIN + ob * 128 + og * 8 + i) * HH + y) * WW + pg * 8;
        *(ulonglong2*)op       = make_ulonglong2(acc[i][0], acc[i][1]);
        *(ulonglong2*)(op + 4) = make_ulonglong2(acc[i][2], acc[i][3]);
    }
}

// ---------------------------------------------------------------------------
extern "C" void kernel_launch(void* const* d_in, const int* in_sizes, int n_in,
                              void* d_out, int out_size) {
    const float* x   = (const float*)d_in[0];   // [2,256,64,64]
    const float* lat = (const float*)d_in[1];   // [2,128,1,1]
    const float* tw  = (const float*)d_in[2];   // [256,128,3,3]
    const float* w1  = (const float*)d_in[3];   // [64,128,3,3]
    const float* b1  = (const float*)d_in[4];   // [64]
    const float* w2  = (const float*)d_in[5];   // [18,64,3,3]
    const float* b2  = (const float*)d_in[6];   // [18]
    float* out = (float*)d_out;                 // [2,256,128,128]

    float* wr_ptr;
    float* wt2_ptr;
    cudaGetSymbolAddress((void**)&wr_ptr, g_wr);
    cudaGetSymbolAddress((void**)&wt2_ptr, g_wt2);

    reorder_kernel<<<(KK * COUT * CIN + 255) / 256, 256>>>(tw);
    offsets_kernel<<<1, 128>>>(lat, w1, b1, w2, b2);
    {
        dim3 grid(HH, 2, NB);   // (Y, x-parity, n)
        tconv_kernel<<<grid, 256>>>(x, wt2_ptr);
    }
    {
        dim3 grid(HH, 2, NB);   // (y, o-tile, n)
        deform_kernel<<<grid, 256>>>(wr_ptr, out);
    }
}

// round 6
// speedup vs baseline: 2.5164x; 2.5164x over previous
#include <cuda_runtime.h>
#include <cuda_bf16.h>
#include <stdint.h>
#include <math.h>

// Problem constants
#define CIN   256
#define COUT  128
#define KK    9
#define H0    64
#define W0    64
#define HH    128
#define WW    128
#define NB    2
#define KTOT  (KK * COUT)        // 1152
#define STAGES (KTOT / 32)       // 36

// ---------------- device scratch (no allocations allowed) ----------------
__device__ __align__(16) float g_wt2[KK * CIN * COUT];      // tconv weights
__device__ __align__(16) float g_upcl[NB * HH * WW * COUT]; // up fp32, channel-last (16MB)
__device__ int   g_sy[NB][KK], g_sx[NB][KK];
__device__ float g_cw[NB][KK][4];
__device__ __align__(16) __nv_bfloat16 g_Whi[CIN * KTOT];   // [o][kk*128+ci]
__device__ __align__(16) __nv_bfloat16 g_Wlo[CIN * KTOT];
__device__ __align__(16) __nv_bfloat16 g_Shi[NB * HH * WW * KTOT]; // 75.5MB
__device__ __align__(16) __nv_bfloat16 g_Slo[NB * HH * WW * KTOT]; // 75.5MB

// ---------------- PTX helpers (all target-independent, sm_80+) ----------------
__device__ __forceinline__ uint32_t s2u(const void* p) {
    uint32_t a;
    asm("{ .reg .u64 t; cvta.to.shared.u64 t, %1; cvt.u32.u64 %0, t; }" : "=r"(a) : "l"(p));
    return a;
}
__device__ __forceinline__ void cp16(uint32_t d, const void* s) {
    asm volatile("cp.async.cg.shared.global [%0], [%1], 16;" :: "r"(d), "l"(s));
}
__device__ __forceinline__ void cp_commit() {
    asm volatile("cp.async.commit_group;" ::: "memory");
}
__device__ __forceinline__ void cp_wait_all() {
    asm volatile("cp.async.wait_group 0;" ::: "memory");
}
__device__ __forceinline__ void ldsm4(uint32_t* r, uint32_t a) {
    asm volatile("ldmatrix.sync.aligned.m8n8.x4.shared.b16 {%0,%1,%2,%3}, [%4];"
                 : "=r"(r[0]), "=r"(r[1]), "=r"(r[2]), "=r"(r[3]) : "r"(a));
}
__device__ __forceinline__ void ldsm2(uint32_t* r, uint32_t a) {
    asm volatile("ldmatrix.sync.aligned.m8n8.x2.shared.b16 {%0,%1}, [%2];"
                 : "=r"(r[0]), "=r"(r[1]) : "r"(a));
}
__device__ __forceinline__ void mma_bf16(float* d, const uint32_t* a, const uint32_t* b) {
    asm volatile(
        "mma.sync.aligned.m16n8k16.row.col.f32.bf16.bf16.f32 "
        "{%0,%1,%2,%3}, {%4,%5,%6,%7}, {%8,%9}, {%0,%1,%2,%3};"
        : "+f"(d[0]), "+f"(d[1]), "+f"(d[2]), "+f"(d[3])
        : "r"(a[0]), "r"(a[1]), "r"(a[2]), "r"(a[3]), "r"(b[0]), "r"(b[1]));
}

union BFP { __nv_bfloat16 b[4]; uint2 v; };

// ---------------------------------------------------------------------------
// Kernel 1: tconv weight reorder  g_wt2[(ky*3+kx)][ci][co] = tw[ci][co][2-ky][2-kx]
// ---------------------------------------------------------------------------
__global__ void reorder_kernel(const float* __restrict__ tw) {
    int i = blockIdx.x * blockDim.x + threadIdx.x;
    if (i >= KK * CIN * COUT) return;
    int co = i & (COUT - 1);
    int ci = (i >> 7) & (CIN - 1);
    int k2 = i >> 15;
    int ky = k2 / 3, kx = k2 % 3;
    g_wt2[i] = tw[(ci * COUT + co) * KK + (2 - ky) * 3 + (2 - kx)];
}

// ---------------------------------------------------------------------------
// Kernel 2: deform weight bf16 hi/lo split, K-contiguous: Whi[o][kk*128+ci]
// ---------------------------------------------------------------------------
__global__ void wsplit_kernel(const float* __restrict__ tw) {
    int i = blockIdx.x * blockDim.x + threadIdx.x;
    if (i >= CIN * KTOT) return;
    int o = i / KTOT, kidx = i % KTOT;
    int kk = kidx >> 7, ci = kidx & 127;
    float w = tw[(o * COUT + ci) * KK + kk];
    __nv_bfloat16 h = __float2bfloat16(w);
    g_Whi[i] = h;
    g_Wlo[i] = __float2bfloat16(w - __bfloat162float(h));
}

// ---------------------------------------------------------------------------
// Kernel 3: offset branch (center-tap only, spatially constant)
// ---------------------------------------------------------------------------
__global__ void offsets_kernel(const float* __restrict__ lat,
                               const float* __restrict__ w1,
                               const float* __restrict__ b1,
                               const float* __restrict__ w2,
                               const float* __restrict__ b2) {
    __shared__ float h[NB][64];
    __shared__ float oc[NB][18];
    int tid = threadIdx.x;
    if (tid < NB * 64) {
        int n = tid >> 6, j = tid & 63;
        float s = b1[j];
        #pragma unroll 4
        for (int i = 0; i < COUT; i++)
            s += lat[n * COUT + i] * w1[(j * COUT + i) * KK + 4];
        h[n][j] = fmaxf(s, 0.f);
    }
    __syncthreads();
    if (tid < NB * 18) {
        int n = tid / 18, c = tid % 18;
        float s = b2[c];
        #pragma unroll 4
        for (int j = 0; j < 64; j++)
            s += h[n][j] * w2[(c * 64 + j) * KK + 4];
        oc[n][c] = tanhf(s);
    }
    __syncthreads();
    if (tid < NB * KK) {
        int n = tid / KK, kk = tid % KK;
        float oy = oc[n][2 * kk], ox = oc[n][2 * kk + 1];
        float fy = floorf(oy), fx = floorf(ox);
        float dy = oy - fy,  dx = ox - fx;
        g_sy[n][kk] = (kk / 3 - 1) + (int)fy;
        g_sx[n][kk] = (kk % 3 - 1) + (int)fx;
        g_cw[n][kk][0] = (1.f - dy) * (1.f - dx);
        g_cw[n][kk][1] = (1.f - dy) * dx;
        g_cw[n][kk][2] = dy * (1.f - dx);
        g_cw[n][kk][3] = dy * dx;
    }
}

// ---------------------------------------------------------------------------
// Kernel 4: transposed conv (R2 GEMM), output fp32 channel-last up_cl[n][y][x][co]
// ---------------------------------------------------------------------------
__global__ void __launch_bounds__(256)
tconv_kernel(const float* __restrict__ x, const float* __restrict__ wt2) {
    const int Y   = blockIdx.x;
    const int sX  = blockIdx.y;
    const int n   = blockIdx.z;
    const int tid = threadIdx.x;

    __shared__ __align__(16) float wA[16][128];
    __shared__ __align__(16) float xs[16][64];

    const int og = tid >> 4;
    const int pg = tid & 15;

    float acc[8][4];
    #pragma unroll
    for (int i = 0; i < 8; i++)
        #pragma unroll
        for (int j = 0; j < 4; j++) acc[i][j] = 0.f;

    int kylist[2]; int nky = 0;
    if (Y & 1) {
        kylist[nky++] = 0;
        if (Y + 1 < HH) kylist[nky++] = 2;
    } else {
        kylist[nky++] = 1;
    }
    int kxlist[2]; int nkx = 0;
    if (sX == 0) { kxlist[nkx++] = 1; }
    else         { kxlist[nkx++] = 0; kxlist[nkx++] = 2; }

    const int co_f = tid & 127, rr_f = tid >> 7;
    const int j_f  = tid & 63,  cr_f = tid >> 6;

    for (int a_ = 0; a_ < nky; a_++) {
        const int ky = kylist[a_];
        const int y0 = (Y + ky - 1) >> 1;
        const float* xbase = x + (n * CIN * H0 + y0) * W0;
        for (int b_ = 0; b_ < nkx; b_++) {
            const int kx = kxlist[b_];
            const int d  = (sX + kx - 1) >> 1;
            const float* wtap = wt2 + (ky * 3 + kx) * CIN * COUT;
            const int src = j_f + d;
            const bool sok = src < W0;

            for (int c0 = 0; c0 < CIN; c0 += 16) {
                #pragma unroll
                for (int r = 0; r < 8; r++)
                    wA[rr_f + 2 * r][co_f] = wtap[(c0 + rr_f + 2 * r) * COUT + co_f];
                #pragma unroll
                for (int r = 0; r < 4; r++) {
                    int ci = cr_f + 4 * r;
                    xs[ci][j_f] = sok ? xbase[(c0 + ci) * H0 * W0 + src] : 0.f;
                }
                __syncthreads();

                #pragma unroll 4
                for (int ci = 0; ci < 16; ci++) {
                    float4 a0 = *(const float4*)&wA[ci][og * 8];
                    float4 a1 = *(const float4*)&wA[ci][og * 8 + 4];
                    float4 b0 = *(const float4*)&xs[ci][pg * 4];
                    float av[8] = {a0.x, a0.y, a0.z, a0.w, a1.x, a1.y, a1.z, a1.w};
                    float bv[4] = {b0.x, b0.y, b0.z, b0.w};
                    #pragma unroll
                    for (int i = 0; i < 8; i++)
                        #pragma unroll
                        for (int j = 0; j < 4; j++)
                            acc[i][j] += av[i] * bv[j];
                }
                __syncthreads();
            }
        }
    }

    #pragma unroll
    for (int j = 0; j < 4; j++) {
        int X = 2 * (pg * 4 + j) + sX;
        float* up = g_upcl + (((size_t)(n * HH + Y) * WW + X) * COUT) + og * 8;
        *(float4*)up       = make_float4(acc[0][j], acc[1][j], acc[2][j], acc[3][j]);
        *(float4*)(up + 4) = make_float4(acc[4][j], acc[5][j], acc[6][j], acc[7][j]);
    }
}

// ---------------------------------------------------------------------------
// Kernel 5: bilinear sampler -> S[n][px][kk*128+ci] bf16 hi/lo.
// Grid (kk, y, n), 256 thr. Warp w handles x = w, w+8, ...; lane -> 4 ci.
// ---------------------------------------------------------------------------
__global__ void __launch_bounds__(256)
sample_kernel() {
    const int kk = blockIdx.x, y = blockIdx.y, n = blockIdx.z;
    const int lane = threadIdx.x & 31, w = threadIdx.x >> 5;
    const int sy = g_sy[n][kk], sx = g_sx[n][kk];
    const float c00 = g_cw[n][kk][0], c01 = g_cw[n][kk][1];
    const float c10 = g_cw[n][kk][2], c11 = g_cw[n][kk][3];
    const float* base = g_upcl + (size_t)n * HH * WW * COUT;
    const int y0 = y + sy;
    const bool yA = (unsigned)y0 < HH, yB = (unsigned)(y0 + 1) < HH;

    for (int x = w; x < WW; x += 8) {
        const int x0 = x + sx;
        const bool xA = (unsigned)x0 < WW, xB = (unsigned)(x0 + 1) < WW;
        float4 v = make_float4(0.f, 0.f, 0.f, 0.f);
        const float* r00 = base + ((size_t)y0 * WW + x0) * COUT + lane * 4;
        if (yA & xA) {
            float4 t = *(const float4*)r00;
            v.x += c00 * t.x; v.y += c00 * t.y; v.z += c00 * t.z; v.w += c00 * t.w;
        }
        if (yA & xB) {
            float4 t = *(const float4*)(r00 + COUT);
            v.x += c01 * t.x; v.y += c01 * t.y; v.z += c01 * t.z; v.w += c01 * t.w;
        }
        if (yB & xA) {
            float4 t = *(const float4*)(r00 + WW * COUT);
            v.x += c10 * t.x; v.y += c10 * t.y; v.z += c10 * t.z; v.w += c10 * t.w;
        }
        if (yB & xB) {
            float4 t = *(const float4*)(r00 + WW * COUT + COUT);
            v.x += c11 * t.x; v.y += c11 * t.y; v.z += c11 * t.z; v.w += c11 * t.w;
        }
        BFP ph, pl;
        float vv[4] = {v.x, v.y, v.z, v.w};
        #pragma unroll
        for (int e = 0; e < 4; e++) {
            __nv_bfloat16 hb = __float2bfloat16(vv[e]);
            ph.b[e] = hb;
            pl.b[e] = __float2bfloat16(vv[e] - __bfloat162float(hb));
        }
        size_t so = ((size_t)((n * HH + y) * WW + x)) * KTOT + kk * COUT + lane * 4;
        *(uint2*)(g_Shi + so) = ph.v;
        *(uint2*)(g_Slo + so) = pl.v;
    }
}

// ---------------------------------------------------------------------------
// Kernel 6: deform GEMM via mma.sync bf16 3-term split.
// Grid (y=128, ob=2, n=2). CTA tile: M=128 (o), N=128 (px), K=1152.
// 8 warps, warp tile 64x32; cp.async double-buffered smem, 80B row stride.
// smem per stage: 4 tiles (Ahi,Alo,Bhi,Blo) x 128 rows x 80B = 40960B; x2 stages.
// ---------------------------------------------------------------------------
__global__ void __launch_bounds__(256, 1)
gemm_kernel(float* __restrict__ out) {
    extern __shared__ __align__(16) unsigned char smraw[];
    const int y   = blockIdx.x;
    const int ob  = blockIdx.y;
    const int n   = blockIdx.z;
    const int tid = threadIdx.x;
    const int lane = tid & 31, warp = tid >> 5;
    const int wm = warp & 1, wn = warp >> 1;

    const uint32_t smb = s2u(smraw);

    const __nv_bfloat16* srcA_h = g_Whi + (size_t)(ob * 128) * KTOT;
    const __nv_bfloat16* srcA_l = g_Wlo + (size_t)(ob * 128) * KTOT;
    const size_t bofs = (size_t)((n * HH + y) * WW) * KTOT;
    const __nv_bfloat16* srcB_h = g_Shi + bofs;
    const __nv_bfloat16* srcB_l = g_Slo + bofs;

    float acc[4][4][4];
    #pragma unroll
    for (int i = 0; i < 4; i++)
        #pragma unroll
        for (int j = 0; j < 4; j++)
            #pragma unroll
            for (int e = 0; e < 4; e++) acc[i][j][e] = 0.f;

    // --- async copy of one stage ---
    auto issue = [&](int s, int buf) {
        const int k0 = s * 32;
        #pragma unroll
        for (int j = 0; j < 8; j++) {
            int chunk = tid + j * 256;          // 0..2047
            int t = chunk >> 9;                 // 0:Ah 1:Al 2:Bh 3:Bl
            int r = (chunk >> 2) & 127;
            int c = chunk & 3;
            uint32_t dst = smb + buf * 40960 + t * 10240 + r * 80 + c * 16;
            const __nv_bfloat16* src;
            int off = r * KTOT + k0 + c * 8;
            if      (t == 0) src = srcA_h + off;
            else if (t == 1) src = srcA_l + off;
            else if (t == 2) src = srcB_h + off;
            else             src = srcB_l + off;
            cp16(dst, src);
        }
        cp_commit();
    };

    issue(0, 0);

    for (int s = 0; s < STAGES; s++) {
        cp_wait_all();
        __syncthreads();
        if (s + 1 < STAGES) issue(s + 1, (s + 1) & 1);

        const int buf = s & 1;
        const uint32_t Ab = smb + buf * 40960;
        const uint32_t Bb = Ab + 20480;

        #pragma unroll
        for (int ks = 0; ks < 2; ks++) {
            uint32_t afr[2][4][4];
            #pragma unroll
            for (int t = 0; t < 2; t++)
                #pragma unroll
                for (int mt = 0; mt < 4; mt++) {
                    uint32_t ad = Ab + t * 10240 +
                        (wm * 64 + mt * 16 + (lane & 15)) * 80 + ks * 32 + (lane >> 4) * 16;
                    ldsm4(afr[t][mt], ad);
                }
            uint32_t bfr[2][4][2];
            #pragma unroll
            for (int t = 0; t < 2; t++)
                #pragma unroll
                for (int nt = 0; nt < 4; nt++) {
                    uint32_t bd = Bb + t * 10240 +
                        (wn * 32 + nt * 8 + (lane & 7)) * 80 + ks * 32 + ((lane >> 3) & 1) * 16;
                    ldsm2(bfr[t][nt], bd);
                }
            #pragma unroll
            for (int mt = 0; mt < 4; mt++)
                #pragma unroll
                for (int nt = 0; nt < 4; nt++) {
                    mma_bf16(acc[mt][nt], afr[0][mt], bfr[0][nt]);   // hi*hi
                    mma_bf16(acc[mt][nt], afr[0][mt], bfr[1][nt]);   // hi*lo
                    mma_bf16(acc[mt][nt], afr[1][mt], bfr[0][nt]);   // lo*hi
                }
        }
        __syncthreads();
    }

    // epilogue: write C[o][x] to out[n][o][y][x]
    #pragma unroll
    for (int mt = 0; mt < 4; mt++) {
        int m = wm * 64 + mt * 16 + (lane >> 2);
        float* pbase = out + (((size_t)(n * CIN + ob * 128 + m) * HH + y) * WW);
        #pragma unroll
        for (int nt = 0; nt < 4; nt++) {
            int xcol = wn * 32 + nt * 8 + (lane & 3) * 2;
            *(float2*)(pbase + xcol) = make_float2(acc[mt][nt][0], acc[mt][nt][1]);
            *(float2*)(pbase + 8 * HH * WW + xcol) = make_float2(acc[mt][nt][2], acc[mt][nt][3]);
        }
    }
}

// ---------------------------------------------------------------------------
extern "C" void kernel_launch(void* const* d_in, const int* in_sizes, int n_in,
                              void* d_out, int out_size) {
    const float* x   = (const float*)d_in[0];
    const float* lat = (const float*)d_in[1];
    const float* tw  = (const float*)d_in[2];
    const float* w1  = (const float*)d_in[3];
    const float* b1  = (const float*)d_in[4];
    const float* w2  = (const float*)d_in[5];
    const float* b2  = (const float*)d_in[6];
    float* out = (float*)d_out;

    float* wt2_ptr;
    cudaGetSymbolAddress((void**)&wt2_ptr, g_wt2);

    cudaFuncSetAttribute(gemm_kernel,
                         cudaFuncAttributeMaxDynamicSharedMemorySize, 81920);

    reorder_kernel<<<(KK * CIN * COUT + 255) / 256, 256>>>(tw);
    wsplit_kernel<<<(CIN * KTOT + 255) / 256, 256>>>(tw);
    offsets_kernel<<<1, 128>>>(lat, w1, b1, w2, b2);
    {
        dim3 grid(HH, 2, NB);
        tconv_kernel<<<grid, 256>>>(x, wt2_ptr);
    }
    {
        dim3 grid(KK, HH, NB);
        sample_kernel<<<grid, 256>>>();
    }
    {
        dim3 grid(HH, 2, NB);
        gemm_kernel<<<grid, 256, 81920>>>(out);
    }
}

// round 7
// speedup vs baseline: 3.1098x; 1.2358x over previous
#include <cuda_runtime.h>
#include <cuda_bf16.h>
#include <stdint.h>
#include <math.h>

// Problem constants
#define CIN   256
#define COUT  128
#define KK    9
#define H0    64
#define W0    64
#define XP    65          // padded x dims (extra zero row/col)
#define HH    128
#define WW    128
#define NB    2
#define KTOT  (KK * COUT)        // 1152
#define STAGES (KTOT / 32)       // 36

// ---------------- device scratch (no allocations allowed) ----------------
__device__ __align__(16) float g_upcl[NB * HH * WW * COUT]; // up fp32, channel-last (16MB)
__device__ int   g_sy[NB][KK], g_sx[NB][KK];
__device__ float g_cw[NB][KK][4];
__device__ __align__(16) __nv_bfloat16 g_Whi[CIN * KTOT];   // deform W [o][kk*128+ci]
__device__ __align__(16) __nv_bfloat16 g_Wlo[CIN * KTOT];
__device__ __align__(16) __nv_bfloat16 g_Shi[NB * HH * WW * KTOT]; // 75.5MB
__device__ __align__(16) __nv_bfloat16 g_Slo[NB * HH * WW * KTOT]; // 75.5MB
__device__ __align__(16) __nv_bfloat16 g_xpad_hi[NB * XP * XP * CIN]; // 4.3MB
__device__ __align__(16) __nv_bfloat16 g_xpad_lo[NB * XP * XP * CIN];
__device__ __align__(16) __nv_bfloat16 g_Wch[COUT * 2304];  // tconv class weights
__device__ __align__(16) __nv_bfloat16 g_Wcl[COUT * 2304];

__constant__ int c_clsBase[4] = {0, 256, 768, 1280};
__constant__ int c_clsK[4]    = {256, 512, 512, 1024};

// ---------------- PTX helpers (target-independent, sm_80+) ----------------
__device__ __forceinline__ uint32_t s2u(const void* p) {
    uint32_t a;
    asm("{ .reg .u64 t; cvta.to.shared.u64 t, %1; cvt.u32.u64 %0, t; }" : "=r"(a) : "l"(p));
    return a;
}
__device__ __forceinline__ void cp16(uint32_t d, const void* s) {
    asm volatile("cp.async.cg.shared.global [%0], [%1], 16;" :: "r"(d), "l"(s));
}
__device__ __forceinline__ void cp_commit() {
    asm volatile("cp.async.commit_group;" ::: "memory");
}
__device__ __forceinline__ void cp_wait_all() {
    asm volatile("cp.async.wait_group 0;" ::: "memory");
}
__device__ __forceinline__ void ldsm4(uint32_t* r, uint32_t a) {
    asm volatile("ldmatrix.sync.aligned.m8n8.x4.shared.b16 {%0,%1,%2,%3}, [%4];"
                 : "=r"(r[0]), "=r"(r[1]), "=r"(r[2]), "=r"(r[3]) : "r"(a));
}
__device__ __forceinline__ void ldsm2(uint32_t* r, uint32_t a) {
    asm volatile("ldmatrix.sync.aligned.m8n8.x2.shared.b16 {%0,%1}, [%2];"
                 : "=r"(r[0]), "=r"(r[1]) : "r"(a));
}
__device__ __forceinline__ void mma_bf16(float* d, const uint32_t* a, const uint32_t* b) {
    asm volatile(
        "mma.sync.aligned.m16n8k16.row.col.f32.bf16.bf16.f32 "
        "{%0,%1,%2,%3}, {%4,%5,%6,%7}, {%8,%9}, {%0,%1,%2,%3};"
        : "+f"(d[0]), "+f"(d[1]), "+f"(d[2]), "+f"(d[3])
        : "r"(a[0]), "r"(a[1]), "r"(a[2]), "r"(a[3]), "r"(b[0]), "r"(b[1]));
}

union BFP { __nv_bfloat16 b[4]; uint2 v; };

// ---------------------------------------------------------------------------
// Kernel 1: deform weight bf16 hi/lo split, K-contiguous: Whi[o][kk*128+ci]
// ---------------------------------------------------------------------------
__global__ void wsplit_kernel(const float* __restrict__ tw) {
    int i = blockIdx.x * blockDim.x + threadIdx.x;
    if (i >= CIN * KTOT) return;
    int o = i / KTOT, kidx = i % KTOT;
    int kk = kidx >> 7, ci = kidx & 127;
    float w = tw[(o * COUT + ci) * KK + kk];
    __nv_bfloat16 h = __float2bfloat16(w);
    g_Whi[i] = h;
    g_Wlo[i] = __float2bfloat16(w - __bfloat162float(h));
}

// ---------------------------------------------------------------------------
// Kernel 2: tconv class weights.
// cls = (Y&1)*2 + sX; tap order a*nkx+b with kys = py?{0,2}:{1}, kxs = pxp?{0,2}:{1}
// Wc[co][base(cls)+tap*256+ci] = tw[ci][co][2-ky][2-kx], split hi/lo.
// ---------------------------------------------------------------------------
__global__ void wclass_kernel(const float* __restrict__ tw) {
    int i = blockIdx.x * blockDim.x + threadIdx.x;
    if (i >= COUT * 2304) return;
    int co = i / 2304, kf = i % 2304;
    int cls = (kf >= 1280) ? 3 : (kf >= 768) ? 2 : (kf >= 256) ? 1 : 0;
    int k = kf - c_clsBase[cls];
    int py = cls >> 1, pxp = cls & 1;
    int nkx = pxp ? 2 : 1;
    int tap = k >> 8, ci = k & 255;
    int a = tap / nkx, b = tap % nkx;
    int ky = py ? (a ? 2 : 0) : 1;
    int kx = pxp ? (b ? 2 : 0) : 1;
    float w = tw[(ci * COUT + co) * KK + (2 - ky) * 3 + (2 - kx)];
    __nv_bfloat16 h = __float2bfloat16(w);
    g_Wch[i] = h;
    g_Wcl[i] = __float2bfloat16(w - __bfloat162float(h));
}

// ---------------------------------------------------------------------------
// Kernel 3: x -> channel-last bf16 hi/lo with zero pad row/col 64.
// Grid (65, NB), 256 threads. smem-transposed for coalescing.
// ---------------------------------------------------------------------------
__global__ void __launch_bounds__(256)
xsplit_kernel(const float* __restrict__ x) {
    const int y0 = blockIdx.x, n = blockIdx.y;
    const int tid = threadIdx.x;
    __nv_bfloat16* oh = g_xpad_hi + (size_t)(n * XP + y0) * XP * CIN;
    __nv_bfloat16* ol = g_xpad_lo + (size_t)(n * XP + y0) * XP * CIN;

    if (y0 == 64) {
        for (int idx = tid; idx < XP * CIN / 8; idx += 256) {
            *(uint4*)(oh + idx * 8) = make_uint4(0, 0, 0, 0);
            *(uint4*)(ol + idx * 8) = make_uint4(0, 0, 0, 0);
        }
        return;
    }
    __shared__ float tile[64][65];
    for (int cc = 0; cc < 4; cc++) {
        #pragma unroll
        for (int r = 0; r < 16; r++) {
            int ci = (tid >> 6) + r * 4;
            int x0 = tid & 63;
            tile[ci][x0] = x[((size_t)(n * CIN + cc * 64 + ci) * H0 + y0) * W0 + x0];
        }
        __syncthreads();
        #pragma unroll
        for (int r = 0; r < 16; r++) {
            int x0 = (tid >> 6) + r * 4;
            int ci = tid & 63;
            float v = tile[ci][x0];
            __nv_bfloat16 h = __float2bfloat16(v);
            oh[x0 * CIN + cc * 64 + ci] = h;
            ol[x0 * CIN + cc * 64 + ci] = __float2bfloat16(v - __bfloat162float(h));
        }
        __syncthreads();
    }
    // zero pad col x0 = 64
    if (tid < CIN) {
        oh[64 * CIN + tid] = __float2bfloat16(0.f);
        ol[64 * CIN + tid] = __float2bfloat16(0.f);
    }
}

// ---------------------------------------------------------------------------
// Kernel 4: offset branch (center-tap only, spatially constant)
// ---------------------------------------------------------------------------
__global__ void offsets_kernel(const float* __restrict__ lat,
                               const float* __restrict__ w1,
                               const float* __restrict__ b1,
                               const float* __restrict__ w2,
                               const float* __restrict__ b2) {
    __shared__ float h[NB][64];
    __shared__ float oc[NB][18];
    int tid = threadIdx.x;
    if (tid < NB * 64) {
        int n = tid >> 6, j = tid & 63;
        float s = b1[j];
        #pragma unroll 4
        for (int i = 0; i < COUT; i++)
            s += lat[n * COUT + i] * w1[(j * COUT + i) * KK + 4];
        h[n][j] = fmaxf(s, 0.f);
    }
    __syncthreads();
    if (tid < NB * 18) {
        int n = tid / 18, c = tid % 18;
        float s = b2[c];
        #pragma unroll 4
        for (int j = 0; j < 64; j++)
            s += h[n][j] * w2[(c * 64 + j) * KK + 4];
        oc[n][c] = tanhf(s);
    }
    __syncthreads();
    if (tid < NB * KK) {
        int n = tid / KK, kk = tid % KK;
        float oy = oc[n][2 * kk], ox = oc[n][2 * kk + 1];
        float fy = floorf(oy), fx = floorf(ox);
        float dy = oy - fy,  dx = ox - fx;
        g_sy[n][kk] = (kk / 3 - 1) + (int)fy;
        g_sx[n][kk] = (kk % 3 - 1) + (int)fx;
        g_cw[n][kk][0] = (1.f - dy) * (1.f - dx);
        g_cw[n][kk][1] = (1.f - dy) * dx;
        g_cw[n][kk][2] = dy * (1.f - dx);
        g_cw[n][kk][3] = dy * dx;
    }
}

// ---------------------------------------------------------------------------
// Kernel 5: transposed conv as per-parity-class HMMA GEMM (3-term bf16 split).
// Grid (Y, sX, n). CTA: M=128 co x N=64 px, K = c_clsK[cls].
// smem/stage: Ah(10240) Al(10240) Bh(5120) Bl(5120) = 30720; x2 buffers.
// ---------------------------------------------------------------------------
__global__ void __launch_bounds__(256, 1)
tconv_gemm_kernel() {
    extern __shared__ __align__(16) unsigned char smraw[];
    const int Y   = blockIdx.x;
    const int pxp = blockIdx.y;
    const int n   = blockIdx.z;
    const int tid = threadIdx.x;
    const int lane = tid & 31, warp = tid >> 5;
    const int wm = warp & 1, wn = warp >> 1;     // M: 2x64, N: 4x16

    const int py  = Y & 1;
    const int cls = py * 2 + pxp;
    const int Kc  = c_clsK[cls];
    const int kbase = c_clsBase[cls];
    const int nkx = pxp ? 2 : 1;
    const int stages = Kc >> 5;
    const int y0b = Y >> 1;
    const uint32_t smb = s2u(smraw);

    const __nv_bfloat16* Ah_src = g_Wch;
    const __nv_bfloat16* Al_src = g_Wcl;
    const __nv_bfloat16* Bh_src = g_xpad_hi + (size_t)n * XP * XP * CIN;
    const __nv_bfloat16* Bl_src = g_xpad_lo + (size_t)n * XP * XP * CIN;

    float acc[4][2][4];
    #pragma unroll
    for (int i = 0; i < 4; i++)
        #pragma unroll
        for (int j = 0; j < 2; j++)
            #pragma unroll
            for (int e = 0; e < 4; e++) acc[i][j][e] = 0.f;

    auto issue = [&](int s, int buf) {
        const int k0 = s * 32;
        const int tap = k0 >> 8;
        const int a = tap / nkx, b = tap % nkx;
        const int yy = y0b + (py ? a : 0);
        const int d  = pxp ? b : 0;
        const int cib = k0 & 255;
        const size_t brow = ((size_t)yy * XP) * CIN;
        #pragma unroll
        for (int j = 0; j < 6; j++) {
            int id = tid + j * 256;            // 0..1535
            uint32_t base = smb + buf * 30720;
            if (id < 1024) {                   // A tiles
                int t = id >> 9;               // 0 hi, 1 lo
                int rid = id & 511;
                int r = rid >> 2, c = rid & 3;
                uint32_t dst = base + t * 10240 + r * 80 + c * 16;
                const __nv_bfloat16* src = (t ? Al_src : Ah_src)
                    + (size_t)r * 2304 + kbase + k0 + c * 8;
                cp16(dst, src);
            } else {                           // B tiles
                int rid = id - 1024;           // 0..511
                int t = rid >> 8;              // 0 hi, 1 lo
                int rr = rid & 255;
                int r = rr >> 2, c = rr & 3;   // r = px 0..63
                uint32_t dst = base + 20480 + t * 5120 + r * 80 + c * 16;
                const __nv_bfloat16* src = (t ? Bl_src : Bh_src)
                    + brow + (size_t)(r + d) * CIN + cib + c * 8;
                cp16(dst, src);
            }
        }
        cp_commit();
    };

    issue(0, 0);

    for (int s = 0; s < stages; s++) {
        cp_wait_all();
        __syncthreads();
        if (s + 1 < stages) issue(s + 1, (s + 1) & 1);

        const int buf = s & 1;
        const uint32_t Ab = smb + buf * 30720;
        const uint32_t Bb = Ab + 20480;

        #pragma unroll
        for (int ks = 0; ks < 2; ks++) {
            uint32_t afr[2][4][4];
            #pragma unroll
            for (int t = 0; t < 2; t++)
                #pragma unroll
                for (int mt = 0; mt < 4; mt++) {
                    uint32_t ad = Ab + t * 10240 +
                        (wm * 64 + mt * 16 + (lane & 15)) * 80 + ks * 32 + (lane >> 4) * 16;
                    ldsm4(afr[t][mt], ad);
                }
            uint32_t bfr[2][2][2];
            #pragma unroll
            for (int t = 0; t < 2; t++)
                #pragma unroll
                for (int nt = 0; nt < 2; nt++) {
                    uint32_t bd = Bb + t * 5120 +
                        (wn * 16 + nt * 8 + (lane & 7)) * 80 + ks * 32 + ((lane >> 3) & 1) * 16;
                    ldsm2(bfr[t][nt], bd);
                }
            #pragma unroll
            for (int mt = 0; mt < 4; mt++)
                #pragma unroll
                for (int nt = 0; nt < 2; nt++) {
                    mma_bf16(acc[mt][nt], afr[0][mt], bfr[0][nt]);   // hi*hi
                    mma_bf16(acc[mt][nt], afr[0][mt], bfr[1][nt]);   // hi*lo
                    mma_bf16(acc[mt][nt], afr[1][mt], bfr[0][nt]);   // lo*hi
                }
        }
        __syncthreads();
    }

    // epilogue: up_cl[n][Y][X=2*px+pxp][co]
    float* up = g_upcl + (size_t)(n * HH + Y) * WW * COUT;
    #pragma unroll
    for (int mt = 0; mt < 4; mt++) {
        int m0 = wm * 64 + mt * 16 + (lane >> 2);
        #pragma unroll
        for (int nt = 0; nt < 2; nt++) {
            int px0 = wn * 16 + nt * 8 + (lane & 3) * 2;
            up[(size_t)(2 * px0 + pxp) * COUT + m0]           = acc[mt][nt][0];
            up[(size_t)(2 * (px0 + 1) + pxp) * COUT + m0]     = acc[mt][nt][1];
            up[(size_t)(2 * px0 + pxp) * COUT + m0 + 8]       = acc[mt][nt][2];
            up[(size_t)(2 * (px0 + 1) + pxp) * COUT + m0 + 8] = acc[mt][nt][3];
        }
    }
}

// ---------------------------------------------------------------------------
// Kernel 6: bilinear sampler -> S[n][px][kk*128+ci] bf16 hi/lo.
// ---------------------------------------------------------------------------
__global__ void __launch_bounds__(256)
sample_kernel() {
    const int kk = blockIdx.x, y = blockIdx.y, n = blockIdx.z;
    const int lane = threadIdx.x & 31, w = threadIdx.x >> 5;
    const int sy = g_sy[n][kk], sx = g_sx[n][kk];
    const float c00 = g_cw[n][kk][0], c01 = g_cw[n][kk][1];
    const float c10 = g_cw[n][kk][2], c11 = g_cw[n][kk][3];
    const float* base = g_upcl + (size_t)n * HH * WW * COUT;
    const int y0 = y + sy;
    const bool yA = (unsigned)y0 < HH, yB = (unsigned)(y0 + 1) < HH;

    for (int x = w; x < WW; x += 8) {
        const int x0 = x + sx;
        const bool xA = (unsigned)x0 < WW, xB = (unsigned)(x0 + 1) < WW;
        float4 v = make_float4(0.f, 0.f, 0.f, 0.f);
        const float* r00 = base + ((size_t)y0 * WW + x0) * COUT + lane * 4;
        if (yA & xA) {
            float4 t = *(const float4*)r00;
            v.x += c00 * t.x; v.y += c00 * t.y; v.z += c00 * t.z; v.w += c00 * t.w;
        }
        if (yA & xB) {
            float4 t = *(const float4*)(r00 + COUT);
            v.x += c01 * t.x; v.y += c01 * t.y; v.z += c01 * t.z; v.w += c01 * t.w;
        }
        if (yB & xA) {
            float4 t = *(const float4*)(r00 + WW * COUT);
            v.x += c10 * t.x; v.y += c10 * t.y; v.z += c10 * t.z; v.w += c10 * t.w;
        }
        if (yB & xB) {
            float4 t = *(const float4*)(r00 + WW * COUT + COUT);
            v.x += c11 * t.x; v.y += c11 * t.y; v.z += c11 * t.z; v.w += c11 * t.w;
        }
        BFP ph, pl;
        float vv[4] = {v.x, v.y, v.z, v.w};
        #pragma unroll
        for (int e = 0; e < 4; e++) {
            __nv_bfloat16 hb = __float2bfloat16(vv[e]);
            ph.b[e] = hb;
            pl.b[e] = __float2bfloat16(vv[e] - __bfloat162float(hb));
        }
        size_t so = ((size_t)((n * HH + y) * WW + x)) * KTOT + kk * COUT + lane * 4;
        *(uint2*)(g_Shi + so) = ph.v;
        *(uint2*)(g_Slo + so) = pl.v;
    }
}

// ---------------------------------------------------------------------------
// Kernel 7: deform GEMM via mma.sync bf16 3-term split (unchanged from R5).
// ---------------------------------------------------------------------------
__global__ void __launch_bounds__(256, 1)
gemm_kernel(float* __restrict__ out) {
    extern __shared__ __align__(16) unsigned char smraw[];
    const int y   = blockIdx.x;
    const int ob  = blockIdx.y;
    const int n   = blockIdx.z;
    const int tid = threadIdx.x;
    const int lane = tid & 31, warp = tid >> 5;
    const int wm = warp & 1, wn = warp >> 1;

    const uint32_t smb = s2u(smraw);

    const __nv_bfloat16* srcA_h = g_Whi + (size_t)(ob * 128) * KTOT;
    const __nv_bfloat16* srcA_l = g_Wlo + (size_t)(ob * 128) * KTOT;
    const size_t bofs = (size_t)((n * HH + y) * WW) * KTOT;
    const __nv_bfloat16* srcB_h = g_Shi + bofs;
    const __nv_bfloat16* srcB_l = g_Slo + bofs;

    float acc[4][4][4];
    #pragma unroll
    for (int i = 0; i < 4; i++)
        #pragma unroll
        for (int j = 0; j < 4; j++)
            #pragma unroll
            for (int e = 0; e < 4; e++) acc[i][j][e] = 0.f;

    auto issue = [&](int s, int buf) {
        const int k0 = s * 32;
        #pragma unroll
        for (int j = 0; j < 8; j++) {
            int chunk = tid + j * 256;
            int t = chunk >> 9;
            int r = (chunk >> 2) & 127;
            int c = chunk & 3;
            uint32_t dst = smb + buf * 40960 + t * 10240 + r * 80 + c * 16;
            const __nv_bfloat16* src;
            int off = r * KTOT + k0 + c * 8;
            if      (t == 0) src = srcA_h + off;
            else if (t == 1) src = srcA_l + off;
            else if (t == 2) src = srcB_h + off;
            else             src = srcB_l + off;
            cp16(dst, src);
        }
        cp_commit();
    };

    issue(0, 0);

    for (int s = 0; s < STAGES; s++) {
        cp_wait_all();
        __syncthreads();
        if (s + 1 < STAGES) issue(s + 1, (s + 1) & 1);

        const int buf = s & 1;
        const uint32_t Ab = smb + buf * 40960;
        const uint32_t Bb = Ab + 20480;

        #pragma unroll
        for (int ks = 0; ks < 2; ks++) {
            uint32_t afr[2][4][4];
            #pragma unroll
            for (int t = 0; t < 2; t++)
                #pragma unroll
                for (int mt = 0; mt < 4; mt++) {
                    uint32_t ad = Ab + t * 10240 +
                        (wm * 64 + mt * 16 + (lane & 15)) * 80 + ks * 32 + (lane >> 4) * 16;
                    ldsm4(afr[t][mt], ad);
                }
            uint32_t bfr[2][4][2];
            #pragma unroll
            for (int t = 0; t < 2; t++)
                #pragma unroll
                for (int nt = 0; nt < 4; nt++) {
                    uint32_t bd = Bb + t * 10240 +
                        (wn * 32 + nt * 8 + (lane & 7)) * 80 + ks * 32 + ((lane >> 3) & 1) * 16;
                    ldsm2(bfr[t][nt], bd);
                }
            #pragma unroll
            for (int mt = 0; mt < 4; mt++)
                #pragma unroll
                for (int nt = 0; nt < 4; nt++) {
                    mma_bf16(acc[mt][nt], afr[0][mt], bfr[0][nt]);
                    mma_bf16(acc[mt][nt], afr[0][mt], bfr[1][nt]);
                    mma_bf16(acc[mt][nt], afr[1][mt], bfr[0][nt]);
                }
        }
        __syncthreads();
    }

    #pragma unroll
    for (int mt = 0; mt < 4; mt++) {
        int m = wm * 64 + mt * 16 + (lane >> 2);
        float* pbase = out + (((size_t)(n * CIN + ob * 128 + m) * HH + y) * WW);
        #pragma unroll
        for (int nt = 0; nt < 4; nt++) {
            int xcol = wn * 32 + nt * 8 + (lane & 3) * 2;
            *(float2*)(pbase + xcol) = make_float2(acc[mt][nt][0], acc[mt][nt][1]);
            *(float2*)(pbase + 8 * HH * WW + xcol) = make_float2(acc[mt][nt][2], acc[mt][nt][3]);
        }
    }
}

// ---------------------------------------------------------------------------
extern "C" void kernel_launch(void* const* d_in, const int* in_sizes, int n_in,
                              void* d_out, int out_size) {
    const float* x   = (const float*)d_in[0];
    const float* lat = (const float*)d_in[1];
    const float* tw  = (const float*)d_in[2];
    const float* w1  = (const float*)d_in[3];
    const float* b1  = (const float*)d_in[4];
    const float* w2  = (const float*)d_in[5];
    const float* b2  = (const float*)d_in[6];
    float* out = (float*)d_out;

    cudaFuncSetAttribute(gemm_kernel,
                         cudaFuncAttributeMaxDynamicSharedMemorySize, 81920);
    cudaFuncSetAttribute(tconv_gemm_kernel,
                         cudaFuncAttributeMaxDynamicSharedMemorySize, 61440);

    wsplit_kernel<<<(CIN * KTOT + 255) / 256, 256>>>(tw);
    wclass_kernel<<<(COUT * 2304 + 255) / 256, 256>>>(tw);
    xsplit_kernel<<<dim3(XP, NB), 256>>>(x);
    offsets_kernel<<<1, 128>>>(lat, w1, b1, w2, b2);
    {
        dim3 grid(HH, 2, NB);
        tconv_gemm_kernel<<<grid, 256, 61440>>>();
    }
    {
        dim3 grid(KK, HH, NB);
        sample_kernel<<<grid, 256>>>();
    }
    {
        dim3 grid(HH, 2, NB);
        gemm_kernel<<<grid, 256, 81920>>>(out);
    }
}

// round 8
// speedup vs baseline: 3.3008x; 1.0614x over previous
#include <cuda_runtime.h>
#include <cuda_bf16.h>
#include <stdint.h>
#include <math.h>

// Problem constants
#define CIN   256
#define COUT  128
#define KK    9
#define H0    64
#define W0    64
#define XP    65          // padded x dims (extra zero row/col)
#define HH    128
#define WW    128
#define NB    2
#define KTOT  (KK * COUT)        // 1152
#define STAGES (KTOT / 32)       // 36

// ---------------- device scratch (no allocations allowed) ----------------
__device__ __align__(16) float g_upcl[NB * HH * WW * COUT]; // up fp32, channel-last (16MB)
__device__ int   g_sy[NB][KK], g_sx[NB][KK];
__device__ float g_cw[NB][KK][4];
__device__ __align__(16) __nv_bfloat16 g_Whi[CIN * KTOT];   // deform W [o][kk*128+ci]
__device__ __align__(16) __nv_bfloat16 g_Wlo[CIN * KTOT];
__device__ __align__(16) __nv_bfloat16 g_Shi[NB * HH * WW * KTOT]; // 75.5MB
__device__ __align__(16) __nv_bfloat16 g_Slo[NB * HH * WW * KTOT]; // 75.5MB
__device__ __align__(16) __nv_bfloat16 g_xpad_hi[NB * XP * XP * CIN]; // 4.3MB
__device__ __align__(16) __nv_bfloat16 g_xpad_lo[NB * XP * XP * CIN];
__device__ __align__(16) __nv_bfloat16 g_Wch[COUT * 2304];  // tconv class weights
__device__ __align__(16) __nv_bfloat16 g_Wcl[COUT * 2304];

__constant__ int c_clsBase[4] = {0, 256, 768, 1280};
__constant__ int c_clsK[4]    = {256, 512, 512, 1024};

// ---------------- PTX helpers (target-independent, sm_80+) ----------------
__device__ __forceinline__ uint32_t s2u(const void* p) {
    uint32_t a;
    asm("{ .reg .u64 t; cvta.to.shared.u64 t, %1; cvt.u32.u64 %0, t; }" : "=r"(a) : "l"(p));
    return a;
}
__device__ __forceinline__ void cp16(uint32_t d, const void* s) {
    asm volatile("cp.async.cg.shared.global [%0], [%1], 16;" :: "r"(d), "l"(s));
}
__device__ __forceinline__ void cp_commit() {
    asm volatile("cp.async.commit_group;" ::: "memory");
}
__device__ __forceinline__ void cp_wait_all() {
    asm volatile("cp.async.wait_group 0;" ::: "memory");
}
__device__ __forceinline__ void cp_wait_1() {
    asm volatile("cp.async.wait_group 1;" ::: "memory");
}
__device__ __forceinline__ void ldsm4(uint32_t* r, uint32_t a) {
    asm volatile("ldmatrix.sync.aligned.m8n8.x4.shared.b16 {%0,%1,%2,%3}, [%4];"
                 : "=r"(r[0]), "=r"(r[1]), "=r"(r[2]), "=r"(r[3]) : "r"(a));
}
__device__ __forceinline__ void ldsm2(uint32_t* r, uint32_t a) {
    asm volatile("ldmatrix.sync.aligned.m8n8.x2.shared.b16 {%0,%1}, [%2];"
                 : "=r"(r[0]), "=r"(r[1]) : "r"(a));
}
__device__ __forceinline__ void mma_bf16(float* d, const uint32_t* a, const uint32_t* b) {
    asm volatile(
        "mma.sync.aligned.m16n8k16.row.col.f32.bf16.bf16.f32 "
        "{%0,%1,%2,%3}, {%4,%5,%6,%7}, {%8,%9}, {%0,%1,%2,%3};"
        : "+f"(d[0]), "+f"(d[1]), "+f"(d[2]), "+f"(d[3])
        : "r"(a[0]), "r"(a[1]), "r"(a[2]), "r"(a[3]), "r"(b[0]), "r"(b[1]));
}

union BFP { __nv_bfloat16 b[4]; uint2 v; };

// ---------------------------------------------------------------------------
// Kernel 1: fused weight preprocessing. Each thread i does BOTH:
//  (a) deform split: Whi/Wlo[o][kk*128+ci]    (294912 elems)
//  (b) tconv class weights Wch/Wcl            (294912 elems)
// ---------------------------------------------------------------------------
__global__ void wprep_kernel(const float* __restrict__ tw) {
    int i = blockIdx.x * blockDim.x + threadIdx.x;
    if (i >= CIN * KTOT) return;
    {   // deform split
        int o = i / KTOT, kidx = i % KTOT;
        int kk = kidx >> 7, ci = kidx & 127;
        float w = tw[(o * COUT + ci) * KK + kk];
        __nv_bfloat16 h = __float2bfloat16(w);
        g_Whi[i] = h;
        g_Wlo[i] = __float2bfloat16(w - __bfloat162float(h));
    }
    {   // tconv class weights
        int co = i / 2304, kf = i % 2304;
        int cls = (kf >= 1280) ? 3 : (kf >= 768) ? 2 : (kf >= 256) ? 1 : 0;
        int k = kf - c_clsBase[cls];
        int py = cls >> 1, pxp = cls & 1;
        int nkx = pxp ? 2 : 1;
        int tap = k >> 8, ci = k & 255;
        int a = tap / nkx, b = tap % nkx;
        int ky = py ? (a ? 2 : 0) : 1;
        int kx = pxp ? (b ? 2 : 0) : 1;
        float w = tw[(ci * COUT + co) * KK + (2 - ky) * 3 + (2 - kx)];
        __nv_bfloat16 h = __float2bfloat16(w);
        g_Wch[i] = h;
        g_Wcl[i] = __float2bfloat16(w - __bfloat162float(h));
    }
}

// ---------------------------------------------------------------------------
// Kernel 2: x -> channel-last bf16 hi/lo with zero pad row/col 64.
// ---------------------------------------------------------------------------
__global__ void __launch_bounds__(256)
xsplit_kernel(const float* __restrict__ x) {
    const int y0 = blockIdx.x, n = blockIdx.y;
    const int tid = threadIdx.x;
    __nv_bfloat16* oh = g_xpad_hi + (size_t)(n * XP + y0) * XP * CIN;
    __nv_bfloat16* ol = g_xpad_lo + (size_t)(n * XP + y0) * XP * CIN;

    if (y0 == 64) {
        for (int idx = tid; idx < XP * CIN / 8; idx += 256) {
            *(uint4*)(oh + idx * 8) = make_uint4(0, 0, 0, 0);
            *(uint4*)(ol + idx * 8) = make_uint4(0, 0, 0, 0);
        }
        return;
    }
    __shared__ float tile[64][65];
    for (int cc = 0; cc < 4; cc++) {
        #pragma unroll
        for (int r = 0; r < 16; r++) {
            int ci = (tid >> 6) + r * 4;
            int x0 = tid & 63;
            tile[ci][x0] = x[((size_t)(n * CIN + cc * 64 + ci) * H0 + y0) * W0 + x0];
        }
        __syncthreads();
        #pragma unroll
        for (int r = 0; r < 16; r++) {
            int x0 = (tid >> 6) + r * 4;
            int ci = tid & 63;
            float v = tile[ci][x0];
            __nv_bfloat16 h = __float2bfloat16(v);
            oh[x0 * CIN + cc * 64 + ci] = h;
            ol[x0 * CIN + cc * 64 + ci] = __float2bfloat16(v - __bfloat162float(h));
        }
        __syncthreads();
    }
    if (tid < CIN) {
        oh[64 * CIN + tid] = __float2bfloat16(0.f);
        ol[64 * CIN + tid] = __float2bfloat16(0.f);
    }
}

// ---------------------------------------------------------------------------
// Kernel 3: offset branch, parallelized: warp-per-output + shfl reductions.
// 1024 threads, one block.
// ---------------------------------------------------------------------------
__global__ void __launch_bounds__(1024)
offsets_kernel(const float* __restrict__ lat,
               const float* __restrict__ w1,
               const float* __restrict__ b1,
               const float* __restrict__ w2,
               const float* __restrict__ b2) {
    __shared__ float h[NB][64];
    __shared__ float oc[NB][18];
    const int tid = threadIdx.x, lane = tid & 31, w = tid >> 5;

    // stage 1: 128 outputs; warp w computes outputs 4w..4w+3 (K=128 each)
    #pragma unroll
    for (int t = 0; t < 4; t++) {
        int o = w * 4 + t;
        int n = o >> 6, j = o & 63;
        float s = 0.f;
        #pragma unroll
        for (int r = 0; r < 4; r++) {
            int i = lane + r * 32;
            s += lat[n * COUT + i] * w1[(j * COUT + i) * KK + 4];
        }
        #pragma unroll
        for (int d = 16; d; d >>= 1) s += __shfl_xor_sync(0xffffffffu, s, d);
        if (lane == 0) h[n][j] = fmaxf(s + b1[j], 0.f);
    }
    __syncthreads();

    // stage 2: 36 outputs; warp w -> outputs w, w+32 (K=64 each)
    for (int o = w; o < NB * 18; o += 32) {
        int n = o / 18, c = o % 18;
        float s = 0.f;
        #pragma unroll
        for (int r = 0; r < 2; r++) {
            int k = lane + r * 32;
            s += h[n][k] * w2[(c * 64 + k) * KK + 4];
        }
        #pragma unroll
        for (int d = 16; d; d >>= 1) s += __shfl_xor_sync(0xffffffffu, s, d);
        if (lane == 0) oc[n][c] = tanhf(s + b2[c]);
    }
    __syncthreads();

    // stage 3: shift/corner decomposition
    if (tid < NB * KK) {
        int n = tid / KK, kk = tid % KK;
        float oy = oc[n][2 * kk], ox = oc[n][2 * kk + 1];
        float fy = floorf(oy), fx = floorf(ox);
        float dy = oy - fy,  dx = ox - fx;
        g_sy[n][kk] = (kk / 3 - 1) + (int)fy;
        g_sx[n][kk] = (kk % 3 - 1) + (int)fx;
        g_cw[n][kk][0] = (1.f - dy) * (1.f - dx);
        g_cw[n][kk][1] = (1.f - dy) * dx;
        g_cw[n][kk][2] = dy * (1.f - dx);
        g_cw[n][kk][3] = dy * dx;
    }
}

// ---------------------------------------------------------------------------
// Kernel 4: transposed conv as per-parity-class HMMA GEMM (3-term bf16 split).
// ---------------------------------------------------------------------------
__global__ void __launch_bounds__(256, 1)
tconv_gemm_kernel() {
    extern __shared__ __align__(16) unsigned char smraw[];
    const int Y   = blockIdx.x;
    const int pxp = blockIdx.y;
    const int n   = blockIdx.z;
    const int tid = threadIdx.x;
    const int lane = tid & 31, warp = tid >> 5;
    const int wm = warp & 1, wn = warp >> 1;     // M: 2x64, N: 4x16

    const int py  = Y & 1;
    const int cls = py * 2 + pxp;
    const int Kc  = c_clsK[cls];
    const int kbase = c_clsBase[cls];
    const int nkx = pxp ? 2 : 1;
    const int stages = Kc >> 5;
    const int y0b = Y >> 1;
    const uint32_t smb = s2u(smraw);

    const __nv_bfloat16* Ah_src = g_Wch;
    const __nv_bfloat16* Al_src = g_Wcl;
    const __nv_bfloat16* Bh_src = g_xpad_hi + (size_t)n * XP * XP * CIN;
    const __nv_bfloat16* Bl_src = g_xpad_lo + (size_t)n * XP * XP * CIN;

    float acc[4][2][4];
    #pragma unroll
    for (int i = 0; i < 4; i++)
        #pragma unroll
        for (int j = 0; j < 2; j++)
            #pragma unroll
            for (int e = 0; e < 4; e++) acc[i][j][e] = 0.f;

    auto issue = [&](int s, int buf) {
        const int k0 = s * 32;
        const int tap = k0 >> 8;
        const int a = tap / nkx, b = tap % nkx;
        const int yy = y0b + (py ? a : 0);
        const int d  = pxp ? b : 0;
        const int cib = k0 & 255;
        const size_t brow = ((size_t)yy * XP) * CIN;
        #pragma unroll
        for (int j = 0; j < 6; j++) {
            int id = tid + j * 256;            // 0..1535
            uint32_t base = smb + buf * 30720;
            if (id < 1024) {                   // A tiles
                int t = id >> 9;
                int rid = id & 511;
                int r = rid >> 2, c = rid & 3;
                uint32_t dst = base + t * 10240 + r * 80 + c * 16;
                const __nv_bfloat16* src = (t ? Al_src : Ah_src)
                    + (size_t)r * 2304 + kbase + k0 + c * 8;
                cp16(dst, src);
            } else {                           // B tiles
                int rid = id - 1024;
                int t = rid >> 8;
                int rr = rid & 255;
                int r = rr >> 2, c = rr & 3;
                uint32_t dst = base + 20480 + t * 5120 + r * 80 + c * 16;
                const __nv_bfloat16* src = (t ? Bl_src : Bh_src)
                    + brow + (size_t)(r + d) * CIN + cib + c * 8;
                cp16(dst, src);
            }
        }
        cp_commit();
    };

    issue(0, 0);

    for (int s = 0; s < stages; s++) {
        cp_wait_all();
        __syncthreads();
        if (s + 1 < stages) issue(s + 1, (s + 1) & 1);

        const int buf = s & 1;
        const uint32_t Ab = smb + buf * 30720;
        const uint32_t Bb = Ab + 20480;

        #pragma unroll
        for (int ks = 0; ks < 2; ks++) {
            uint32_t afr[2][4][4];
            #pragma unroll
            for (int t = 0; t < 2; t++)
                #pragma unroll
                for (int mt = 0; mt < 4; mt++) {
                    uint32_t ad = Ab + t * 10240 +
                        (wm * 64 + mt * 16 + (lane & 15)) * 80 + ks * 32 + (lane >> 4) * 16;
                    ldsm4(afr[t][mt], ad);
                }
            uint32_t bfr[2][2][2];
            #pragma unroll
            for (int t = 0; t < 2; t++)
                #pragma unroll
                for (int nt = 0; nt < 2; nt++) {
                    uint32_t bd = Bb + t * 5120 +
                        (wn * 16 + nt * 8 + (lane & 7)) * 80 + ks * 32 + ((lane >> 3) & 1) * 16;
                    ldsm2(bfr[t][nt], bd);
                }
            #pragma unroll
            for (int mt = 0; mt < 4; mt++)
                #pragma unroll
                for (int nt = 0; nt < 2; nt++) {
                    mma_bf16(acc[mt][nt], afr[0][mt], bfr[0][nt]);
                    mma_bf16(acc[mt][nt], afr[0][mt], bfr[1][nt]);
                    mma_bf16(acc[mt][nt], afr[1][mt], bfr[0][nt]);
                }
        }
        __syncthreads();
    }

    float* up = g_upcl + (size_t)(n * HH + Y) * WW * COUT;
    #pragma unroll
    for (int mt = 0; mt < 4; mt++) {
        int m0 = wm * 64 + mt * 16 + (lane >> 2);
        #pragma unroll
        for (int nt = 0; nt < 2; nt++) {
            int px0 = wn * 16 + nt * 8 + (lane & 3) * 2;
            up[(size_t)(2 * px0 + pxp) * COUT + m0]           = acc[mt][nt][0];
            up[(size_t)(2 * (px0 + 1) + pxp) * COUT + m0]     = acc[mt][nt][1];
            up[(size_t)(2 * px0 + pxp) * COUT + m0 + 8]       = acc[mt][nt][2];
            up[(size_t)(2 * (px0 + 1) + pxp) * COUT + m0 + 8] = acc[mt][nt][3];
        }
    }
}

// ---------------------------------------------------------------------------
// Kernel 5: bilinear sampler -> S[n][px][kk*128+ci] bf16 hi/lo.
// ---------------------------------------------------------------------------
__global__ void __launch_bounds__(256)
sample_kernel() {
    const int kk = blockIdx.x, y = blockIdx.y, n = blockIdx.z;
    const int lane = threadIdx.x & 31, w = threadIdx.x >> 5;
    const int sy = g_sy[n][kk], sx = g_sx[n][kk];
    const float c00 = g_cw[n][kk][0], c01 = g_cw[n][kk][1];
    const float c10 = g_cw[n][kk][2], c11 = g_cw[n][kk][3];
    const float* base = g_upcl + (size_t)n * HH * WW * COUT;
    const int y0 = y + sy;
    const bool yA = (unsigned)y0 < HH, yB = (unsigned)(y0 + 1) < HH;

    for (int x = w; x < WW; x += 8) {
        const int x0 = x + sx;
        const bool xA = (unsigned)x0 < WW, xB = (unsigned)(x0 + 1) < WW;
        float4 v = make_float4(0.f, 0.f, 0.f, 0.f);
        const float* r00 = base + ((size_t)y0 * WW + x0) * COUT + lane * 4;
        if (yA & xA) {
            float4 t = *(const float4*)r00;
            v.x += c00 * t.x; v.y += c00 * t.y; v.z += c00 * t.z; v.w += c00 * t.w;
        }
        if (yA & xB) {
            float4 t = *(const float4*)(r00 + COUT);
            v.x += c01 * t.x; v.y += c01 * t.y; v.z += c01 * t.z; v.w += c01 * t.w;
        }
        if (yB & xA) {
            float4 t = *(const float4*)(r00 + WW * COUT);
            v.x += c10 * t.x; v.y += c10 * t.y; v.z += c10 * t.z; v.w += c10 * t.w;
        }
        if (yB & xB) {
            float4 t = *(const float4*)(r00 + WW * COUT + COUT);
            v.x += c11 * t.x; v.y += c11 * t.y; v.z += c11 * t.z; v.w += c11 * t.w;
        }
        BFP ph, pl;
        float vv[4] = {v.x, v.y, v.z, v.w};
        #pragma unroll
        for (int e = 0; e < 4; e++) {
            __nv_bfloat16 hb = __float2bfloat16(vv[e]);
            ph.b[e] = hb;
            pl.b[e] = __float2bfloat16(vv[e] - __bfloat162float(hb));
        }
        size_t so = ((size_t)((n * HH + y) * WW + x)) * KTOT + kk * COUT + lane * 4;
        *(uint2*)(g_Shi + so) = ph.v;
        *(uint2*)(g_Slo + so) = pl.v;
    }
}

// ---------------------------------------------------------------------------
// Kernel 6: deform GEMM, 3-stage cp.async ring (wait_group 1).
// ---------------------------------------------------------------------------
__global__ void __launch_bounds__(256, 1)
gemm_kernel(float* __restrict__ out) {
    extern __shared__ __align__(16) unsigned char smraw[];
    const int y   = blockIdx.x;
    const int ob  = blockIdx.y;
    const int n   = blockIdx.z;
    const int tid = threadIdx.x;
    const int lane = tid & 31, warp = tid >> 5;
    const int wm = warp & 1, wn = warp >> 1;

    const uint32_t smb = s2u(smraw);

    const __nv_bfloat16* srcA_h = g_Whi + (size_t)(ob * 128) * KTOT;
    const __nv_bfloat16* srcA_l = g_Wlo + (size_t)(ob * 128) * KTOT;
    const size_t bofs = (size_t)((n * HH + y) * WW) * KTOT;
    const __nv_bfloat16* srcB_h = g_Shi + bofs;
    const __nv_bfloat16* srcB_l = g_Slo + bofs;

    float acc[4][4][4];
    #pragma unroll
    for (int i = 0; i < 4; i++)
        #pragma unroll
        for (int j = 0; j < 4; j++)
            #pragma unroll
            for (int e = 0; e < 4; e++) acc[i][j][e] = 0.f;

    auto issue = [&](int s, int buf) {
        const int k0 = s * 32;
        #pragma unroll
        for (int j = 0; j < 8; j++) {
            int chunk = tid + j * 256;
            int t = chunk >> 9;
            int r = (chunk >> 2) & 127;
            int c = chunk & 3;
            uint32_t dst = smb + buf * 40960 + t * 10240 + r * 80 + c * 16;
            const __nv_bfloat16* src;
            int off = r * KTOT + k0 + c * 8;
            if      (t == 0) src = srcA_h + off;
            else if (t == 1) src = srcA_l + off;
            else if (t == 2) src = srcB_h + off;
            else             src = srcB_l + off;
            cp16(dst, src);
        }
        cp_commit();
    };

    issue(0, 0);
    issue(1, 1);

    for (int s = 0; s < STAGES; s++) {
        cp_wait_1();            // stage s copy complete (<=1 group pending)
        __syncthreads();        // also: all warps done computing stage s-1
        if (s + 2 < STAGES) issue(s + 2, (s + 2) % 3);

        const int buf = s % 3;
        const uint32_t Ab = smb + buf * 40960;
        const uint32_t Bb = Ab + 20480;

        #pragma unroll
        for (int ks = 0; ks < 2; ks++) {
            uint32_t afr[2][4][4];
            #pragma unroll
            for (int t = 0; t < 2; t++)
                #pragma unroll
                for (int mt = 0; mt < 4; mt++) {
                    uint32_t ad = Ab + t * 10240 +
                        (wm * 64 + mt * 16 + (lane & 15)) * 80 + ks * 32 + (lane >> 4) * 16;
                    ldsm4(afr[t][mt], ad);
                }
            uint32_t bfr[2][4][2];
            #pragma unroll
            for (int t = 0; t < 2; t++)
                #pragma unroll
                for (int nt = 0; nt < 4; nt++) {
                    uint32_t bd = Bb + t * 10240 +
                        (wn * 32 + nt * 8 + (lane & 7)) * 80 + ks * 32 + ((lane >> 3) & 1) * 16;
                    ldsm2(bfr[t][nt], bd);
                }
            #pragma unroll
            for (int mt = 0; mt < 4; mt++)
                #pragma unroll
                for (int nt = 0; nt < 4; nt++) {
                    mma_bf16(acc[mt][nt], afr[0][mt], bfr[0][nt]);
                    mma_bf16(acc[mt][nt], afr[0][mt], bfr[1][nt]);
                    mma_bf16(acc[mt][nt], afr[1][mt], bfr[0][nt]);
                }
        }
    }

    #pragma unroll
    for (int mt = 0; mt < 4; mt++) {
        int m = wm * 64 + mt * 16 + (lane >> 2);
        float* pbase = out + (((size_t)(n * CIN + ob * 128 + m) * HH + y) * WW);
        #pragma unroll
        for (int nt = 0; nt < 4; nt++) {
            int xcol = wn * 32 + nt * 8 + (lane & 3) * 2;
            *(float2*)(pbase + xcol) = make_float2(acc[mt][nt][0], acc[mt][nt][1]);
            *(float2*)(pbase + 8 * HH * WW + xcol) = make_float2(acc[mt][nt][2], acc[mt][nt][3]);
        }
    }
}

// ---------------------------------------------------------------------------
extern "C" void kernel_launch(void* const* d_in, const int* in_sizes, int n_in,
                              void* d_out, int out_size) {
    const float* x   = (const float*)d_in[0];
    const float* lat = (const float*)d_in[1];
    const float* tw  = (const float*)d_in[2];
    const float* w1  = (const float*)d_in[3];
    const float* b1  = (const float*)d_in[4];
    const float* w2  = (const float*)d_in[5];
    const float* b2  = (const float*)d_in[6];
    float* out = (float*)d_out;

    cudaFuncSetAttribute(gemm_kernel,
                         cudaFuncAttributeMaxDynamicSharedMemorySize, 122880);
    cudaFuncSetAttribute(tconv_gemm_kernel,
                         cudaFuncAttributeMaxDynamicSharedMemorySize, 61440);

    wprep_kernel<<<(CIN * KTOT + 255) / 256, 256>>>(tw);
    xsplit_kernel<<<dim3(XP, NB), 256>>>(x);
    offsets_kernel<<<1, 1024>>>(lat, w1, b1, w2, b2);
    {
        dim3 grid(HH, 2, NB);
        tconv_gemm_kernel<<<grid, 256, 61440>>>();
    }
    {
        dim3 grid(KK, HH, NB);
        sample_kernel<<<grid, 256>>>();
    }
    {
        dim3 grid(HH, 2, NB);
        gemm_kernel<<<grid, 256, 122880>>>(out);
    }
}